// round 10
// baseline (speedup 1.0000x reference)
#include <cuda_runtime.h>

// BinaryTree collocation probability — 8-lane groups, 3-step reduce.
//   x = W[v_j + 2^20 - 1];  path[l] = ((u_k + 2^20) >> (20 - l)) - 1
//   out = prod_{l=0..20} sigmoid( dot(W[path[l]], x) )
//
// Kernel is at a latency floor; only the post-load dependency chain moves the
// needle. 16 groups (8 lanes) x 2 levels = 32 slots, 21 valid. Each lane holds
// 4 float4 of x and of each node row -> 4 parallel dot4 chains, 3-step
// shfl-add reduce (was 4). Product: lanes 0..1 per group hold sigmoids, so
// xor1 forms the group product, xor8+xor16 combine the 4 groups per warp
// (3 shfl-mults total). One smem float per warp, cheap 4-warp barrier.

#define DEPTH   20
#define NLEVELS (DEPTH + 1)      // 21
#define NWARPS  4
#define LPG     2                // levels per 8-lane group
#define NTHREADS (NWARPS * 32)   // 128

__global__ void __launch_bounds__(NTHREADS, 1)
binary_tree_kernel(const float* __restrict__ W,
                   const int* __restrict__ v_j_idx,
                   const int* __restrict__ u_k_idx,
                   float* __restrict__ out)
{
    __shared__ float s_p[NWARPS];

    const int tid   = threadIdx.x;
    const int wid   = tid >> 5;
    const int glane = tid & 7;             // lane within 8-lane group
    const int group = tid >> 3;            // 0..15

    // Hop 1: scalar indices (broadcast loads, one line each).
    const int v_j = __ldg(v_j_idx);
    const int u_k = __ldg(u_k_idx);

    const char* base = (const char*)W;
    const unsigned leaf_off_b = ((unsigned)v_j + ((1u << DEPTH) - 1u)) << 9;
    const int      t          = u_k + (1 << DEPTH);

    // Hop 2: x row — 4 float4 per lane (8 lanes * 4 = 32 float4 = 128 dims).
    const float4* xv = (const float4*)(base + leaf_off_b);
    const float4  x0 = __ldg(xv + glane);
    const float4  x1 = __ldg(xv + glane + 8);
    const float4  x2 = __ldg(xv + glane + 16);
    const float4  x3 = __ldg(xv + glane + 24);

    // 2 levels per group; invalid slots contribute sig = 1 downstream.
    float s[LPG];
    #pragma unroll
    for (int i = 0; i < LPG; ++i) {
        const int level = group * LPG + i;
        s[i] = 0.0f;
        if (level < NLEVELS) {
            const unsigned node_off_b = (unsigned)((t >> (DEPTH - level)) - 1) << 9;
            const float4* nv = (const float4*)(base + node_off_b);
            const float4  a0 = __ldg(nv + glane);
            const float4  a1 = __ldg(nv + glane + 8);
            const float4  a2 = __ldg(nv + glane + 16);
            const float4  a3 = __ldg(nv + glane + 24);
            // four parallel dot4 chains, 2-level combining add
            float d0 = a0.x * x0.x + a0.y * x0.y + a0.z * x0.z + a0.w * x0.w;
            float d1 = a1.x * x1.x + a1.y * x1.y + a1.z * x1.z + a1.w * x1.w;
            float d2 = a2.x * x2.x + a2.y * x2.y + a2.z * x2.z + a2.w * x2.w;
            float d3 = a3.x * x3.x + a3.y * x3.y + a3.z * x3.z + a3.w * x3.w;
            s[i] = (d0 + d1) + (d2 + d3);
        }
    }

    // 3-step shfl reduce within each 8-lane group (offsets < 8 stay in-group).
    #pragma unroll
    for (int off = 4; off > 0; off >>= 1) {
        #pragma unroll
        for (int i = 0; i < LPG; ++i)
            s[i] += __shfl_xor_sync(0xFFFFFFFFu, s[i], off);
    }

    // Lanes 0..1 of each group: one sigmoid each (parallel MUFU). Others: 1.
    float sig = 1.0f;
    if (glane < LPG) {
        const int level = group * LPG + glane;
        if (level < NLEVELS) {
            const float sv = (glane == 0) ? s[0] : s[1];
            sig = __fdividef(1.0f, 1.0f + __expf(-sv));
        }
    }

    // xor1: group product lands in lanes 0,1 (lanes 2..7 hold 1).
    // xor8, xor16: lane 0 of each group combines the 4 group products per warp.
    sig *= __shfl_xor_sync(0xFFFFFFFFu, sig, 1);
    sig *= __shfl_xor_sync(0xFFFFFFFFu, sig, 8);
    sig *= __shfl_xor_sync(0xFFFFFFFFu, sig, 16);

    if ((tid & 31) == 0) s_p[wid] = sig;
    __syncthreads();

    if (tid == 0)
        out[0] = (s_p[0] * s_p[1]) * (s_p[2] * s_p[3]);
}

extern "C" void kernel_launch(void* const* d_in, const int* in_sizes, int n_in,
                              void* d_out, int out_size)
{
    const float* W   = (const float*)d_in[0];
    const int*   vj  = (const int*)d_in[1];
    const int*   uk  = (const int*)d_in[2];
    float*       out = (float*)d_out;

    binary_tree_kernel<<<1, NTHREADS>>>(W, vj, uk, out);
}

// round 11
// speedup vs baseline: 1.0338x; 1.0338x over previous
#include <cuda_runtime.h>

// BinaryTree collocation probability — tail-chain-minimized, 4 warps.
// (Round-7 configuration — best measured: 4.61us harness / 4.70us ncu.
//  Round-10's 8-lane variant regressed to 5.44us ncu: halving shfl depth
//  cost a 2x longer per-thread load-issue sequence. This 16-lane layout is
//  the measured optimum of the chain-length vs load-sequence trade.)
//
//   x = W[v_j + 2^20 - 1];  path[l] = ((u_k + 2^20) >> (20 - l)) - 1
//   out = prod_{l=0..20} sigmoid( dot(W[path[l]], x) )
//
// 8 groups (4 warps x 2 half-warps) x 3 levels; 16 lanes per level with
// 2 float4/lane -> 4-step shfl-add reduce; sigmoids on lanes 0..2 of each
// group; product via xor1+xor2 then xor16 across halves; one smem float
// per warp; 3-FMUL epilogue.

#define DEPTH   20
#define NLEVELS (DEPTH + 1)      // 21
#define NWARPS  4
#define LPG     3                // levels per 16-lane group; 8 groups * 3 = 24 slots
#define NTHREADS (NWARPS * 32)   // 128

__global__ void __launch_bounds__(NTHREADS, 1)
binary_tree_kernel(const float* __restrict__ W,
                   const int* __restrict__ v_j_idx,
                   const int* __restrict__ u_k_idx,
                   float* __restrict__ out)
{
    __shared__ float s_p[NWARPS];

    const int tid   = threadIdx.x;
    const int wid   = tid >> 5;
    const int glane = tid & 15;            // lane within 16-lane group
    const int group = tid >> 4;            // 0..7

    // Hop 1: scalar indices (broadcast loads).
    const int v_j = __ldg(v_j_idx);
    const int u_k = __ldg(u_k_idx);

    const char* base = (const char*)W;
    const unsigned leaf_off_b = ((unsigned)v_j + ((1u << DEPTH) - 1u)) << 9;
    const int      t          = u_k + (1 << DEPTH);

    // Hop 2: x row — 2 float4 per lane (32 float4 = 128 dims per 16 lanes).
    const float4* xv = (const float4*)(base + leaf_off_b);
    const float4  x0 = __ldg(xv + glane);
    const float4  x1 = __ldg(xv + glane + 16);

    // 3 levels per group; invalid slots (group 7) contribute sig = 1.
    float s[LPG];
    #pragma unroll
    for (int i = 0; i < LPG; ++i) {
        const int level = group * LPG + i;
        s[i] = 0.0f;
        if (level < NLEVELS) {
            const unsigned node_off_b = (unsigned)((t >> (DEPTH - level)) - 1) << 9;
            const float4* nv = (const float4*)(base + node_off_b);
            const float4  a0 = __ldg(nv + glane);
            const float4  a1 = __ldg(nv + glane + 16);
            // two parallel dot4 chains, one combining add
            float d0 = a0.x * x0.x + a0.y * x0.y + a0.z * x0.z + a0.w * x0.w;
            float d1 = a1.x * x1.x + a1.y * x1.y + a1.z * x1.z + a1.w * x1.w;
            s[i] = d0 + d1;
        }
    }

    // 4-step shfl reduce within each 16-lane half (offsets < 16 stay in-half).
    #pragma unroll
    for (int off = 8; off > 0; off >>= 1) {
        #pragma unroll
        for (int i = 0; i < LPG; ++i)
            s[i] += __shfl_xor_sync(0xFFFFFFFFu, s[i], off);
    }

    // Lanes 0..2 of each group: one sigmoid each (parallel MUFU). Others: 1.
    float sig = 1.0f;
    if (glane < LPG) {
        const int level = group * LPG + glane;
        if (level < NLEVELS) {
            // static selection (no dynamic register indexing)
            const float sv = (glane == 0) ? s[0] : ((glane == 1) ? s[1] : s[2]);
            sig = __fdividef(1.0f, 1.0f + __expf(-sv));
        }
    }

    // Product over lanes 0..3 of each group (lane 3 holds 1), then across halves.
    sig *= __shfl_xor_sync(0xFFFFFFFFu, sig, 1);
    sig *= __shfl_xor_sync(0xFFFFFFFFu, sig, 2);
    sig *= __shfl_xor_sync(0xFFFFFFFFu, sig, 16);   // combine the two 16-lane halves

    if ((tid & 31) == 0) s_p[wid] = sig;
    __syncthreads();

    if (tid == 0)
        out[0] = (s_p[0] * s_p[1]) * (s_p[2] * s_p[3]);
}

extern "C" void kernel_launch(void* const* d_in, const int* in_sizes, int n_in,
                              void* d_out, int out_size)
{
    const float* W   = (const float*)d_in[0];
    const int*   vj  = (const int*)d_in[1];
    const int*   uk  = (const int*)d_in[2];
    float*       out = (float*)d_out;

    binary_tree_kernel<<<1, NTHREADS>>>(W, vj, uk, out);
}